// round 2
// baseline (speedup 1.0000x reference)
#include <cuda_runtime.h>
#include <cuda_bf16.h>
#include <cstdint>

#define BB   512
#define CC   3
#define TT   500
#define DD   40
#define CD   120
#define NN   256
#define OUTN 12
#define BN   (BB*NN)        // 131072
#define SW   (BN/32)        // 4096 bit-words per timestep
#define B_J0 0.01f
#define BETA 1.8f

// ------------------------- device scratch (allocation-guard-safe) -----------
__device__ float    g_i1[(size_t)TT * BB * NN];     // 262 MB
__device__ unsigned g_s1[(size_t)TT * SW];          // 8.2 MB
__device__ float2   g_W2inT[NN * 128];              // [j][pair(l, l+128)]
__device__ float2   g_W2recT[NN * 128];
__device__ float    g_acc[BB * OUTN];

// ------------------------- packed f32x2 helpers -----------------------------
__device__ __forceinline__ unsigned long long pack_dup(float a) {
    unsigned long long r;
    asm("mov.b64 %0, {%1,%1};" : "=l"(r) : "f"(a));
    return r;
}
__device__ __forceinline__ void unpack2(unsigned long long v, float& a, float& b) {
    asm("mov.b64 {%0,%1}, %2;" : "=f"(a), "=f"(b) : "l"(v));
}
__device__ __forceinline__ void fma2(unsigned long long& acc,
                                     unsigned long long a, unsigned long long b) {
    asm("fma.rn.f32x2 %0, %1, %2, %0;" : "+l"(acc) : "l"(a), "l"(b));
}

// ------------------------- K0: transpose W2 matrices ------------------------
// W2inT[j].pair(l) = (W2_in[l][j], W2_in[l+128][j])   (j = presyn neuron)
__global__ void k0_transpose(const float* __restrict__ W2_in,
                             const float* __restrict__ W2_rec)
{
    int j = blockIdx.x;        // 0..255
    int l = threadIdx.x;       // 0..127
    g_W2inT [j * 128 + l] = make_float2(W2_in [l * NN + j], W2_in [(l + 128) * NN + j]);
    g_W2recT[j * 128 + l] = make_float2(W2_rec[l * NN + j], W2_rec[(l + 128) * NN + j]);
}

// ------------------------- K1: spikify + i1 GEMM ----------------------------
// grid 4000 blocks x 256 threads. Block handles 64 consecutive (t,b) rows
// (all same t since 64 | 512) x all 256 output neurons.
// smem: w1t[120][256] (122880 B) + xsT[120][64] (30720 B) = 153600 B
__global__ void __launch_bounds__(256, 1)
k1_gemm1(const float* __restrict__ x, const float* __restrict__ thrp,
         const float* __restrict__ W1, const float* __restrict__ b1)
{
    extern __shared__ float sm[];
    float* w1t = sm;              // [k][n]
    float* xsT = sm + CD * NN;    // [k][r]

    const int tid = threadIdx.x;
    const int p0  = blockIdx.x * 64;
    const int t   = p0 >> 9;          // p0 / 512
    const int b0  = p0 & 511;
    const float thr = *thrp;

    // load W1 (coalesced float4) -> transposed smem
    for (int i = tid; i < NN * 30; i += 256) {
        float4 v = reinterpret_cast<const float4*>(W1)[i];
        int n = i / 30;
        int k = (i % 30) * 4;
        w1t[(k + 0) * NN + n] = v.x;
        w1t[(k + 1) * NN + n] = v.y;
        w1t[(k + 2) * NN + n] = v.z;
        w1t[(k + 3) * NN + n] = v.w;
    }
    // spikify x -> xsT[k][r]
    for (int i = tid; i < 64 * CD; i += 256) {
        int r  = i / CD;
        int cd = i % CD;
        int c  = cd / DD, d = cd % DD;
        int b  = b0 + r;
        float xv = x[(((size_t)b * CC + c) * TT + t) * DD + d];
        float s  = (xv > thr) ? 1.0f : ((xv < -thr) ? -1.0f : 0.0f);
        xsT[cd * 64 + r] = s;
    }
    __syncthreads();

    const int n = tid;
    unsigned long long acc2[32];
    const unsigned long long zz = pack_dup(0.0f);
    #pragma unroll
    for (int m = 0; m < 32; m++) acc2[m] = zz;

    for (int k = 0; k < CD; k++) {
        unsigned long long wd = pack_dup(w1t[k * NN + n]);
        const ulonglong2* xr = reinterpret_cast<const ulonglong2*>(&xsT[k * 64]);
        #pragma unroll
        for (int m = 0; m < 16; m++) {
            ulonglong2 e = xr[m];
            fma2(acc2[2 * m],     wd, e.x);
            fma2(acc2[2 * m + 1], wd, e.y);
        }
    }

    const float b1v = b1[n];
    size_t base = (size_t)t * BN + (size_t)b0 * NN + n;
    #pragma unroll
    for (int m = 0; m < 32; m++) {
        float lo, hi;
        unpack2(acc2[m], lo, hi);
        g_i1[base + (size_t)(2 * m)     * NN] = lo + b1v;
        g_i1[base + (size_t)(2 * m + 1) * NN] = hi + b1v;
    }
}

// ------------------------- K2: layer-1 ALIF scan -> s1 bits -----------------
__global__ void __launch_bounds__(256)
k2_scan1(const float* __restrict__ tau_adp1, const float* __restrict__ tau_m1)
{
    const int gid  = blockIdx.x * 256 + threadIdx.x;  // b*256 + n
    const int nidx = gid & 255;
    const int lane = threadIdx.x & 31;
    const unsigned wordIdx = gid >> 5;                // b*8 + n/32

    const float alpha = __expf(-1.0f / tau_m1[nidx]);
    const float rho   = __expf(-1.0f / tau_adp1[nidx]);
    const float ca = 1.0f - alpha, cr = 1.0f - rho;

    float m = 0.f, a = B_J0, s = 0.f;
    const float* ip = g_i1 + gid;

    for (int t = 0; t < TT; t += 4) {
        float iv[4];
        #pragma unroll
        for (int k = 0; k < 4; k++) iv[k] = ip[(size_t)(t + k) * BN];
        #pragma unroll
        for (int k = 0; k < 4; k++) {
            a = rho * a + cr * s;
            float Bth = B_J0 + BETA * a;
            m = alpha * m + ca * iv[k] - Bth * s;
            s = (m - Bth > 0.f) ? 1.f : 0.f;
            unsigned bal = __ballot_sync(0xffffffffu, s > 0.5f);
            if (lane == 0) g_s1[(size_t)(t + k) * SW + wordIdx] = bal;
        }
    }
}

// ------------------------- K3: sequential layer-2 + layer-3 -----------------
// grid 512 blocks (one per batch) x 128 threads (thread l owns neurons l, l+128)
__global__ void __launch_bounds__(128)
k3_recurrent(const float* __restrict__ b2_in,  const float* __restrict__ b2_rec,
             const float* __restrict__ W3,     const float* __restrict__ b3,
             const float* __restrict__ tau_adp2, const float* __restrict__ tau_m2,
             const float* __restrict__ tau_m3)
{
    __shared__ float    W3s[OUTN * 257];     // padded rows: conflict-free
    __shared__ unsigned s1w[8];
    __shared__ unsigned s2w[2][8];

    const int b   = blockIdx.x;
    const int l   = threadIdx.x;
    const int wid = l >> 5;

    for (int i = l; i < OUTN * NN; i += 128) {
        W3s[(i >> 8) * 257 + (i & 255)] = W3[i];
    }
    if (l < 8) { s2w[0][l] = 0u; s2w[1][l] = 0u; }

    const int n0 = l, n1 = l + 128;
    const float al_a = __expf(-1.0f / tau_m2[n0]),  al_b = __expf(-1.0f / tau_m2[n1]);
    const float rh_a = __expf(-1.0f / tau_adp2[n0]), rh_b = __expf(-1.0f / tau_adp2[n1]);
    const float bia  = b2_in[n0] + b2_rec[n0];
    const float bib  = b2_in[n1] + b2_rec[n1];

    float m2a = 0.f, m2b = 0.f, a2a = B_J0, a2b = B_J0, s2a = 0.f, s2b = 0.f;

    // layer-3 state (threads 0..11)
    float al3 = 1.f, m3 = 0.f, accr = 0.f, b3v = 0.f;
    if (l < OUTN) { al3 = __expf(-1.0f / tau_m3[l]); b3v = b3[l]; }

    const unsigned s1base = (unsigned)b * 8;
    __syncthreads();

    for (int t = 0; t < TT; t++) {
        const int cur = t & 1, nxt = cur ^ 1;
        if (l < 8) s1w[l] = g_s1[(size_t)t * SW + s1base + l];
        __syncthreads();

        float i2a = bia, i2b = bib;
        #pragma unroll
        for (int w = 0; w < 8; w++) {
            unsigned m = s1w[w];
            const float2* base = g_W2inT + (w * 32) * 128 + l;
            while (m) {
                int j = __ffs((int)m) - 1;
                m &= m - 1;
                float2 v = base[j * 128];
                i2a += v.x; i2b += v.y;
            }
        }
        #pragma unroll
        for (int w = 0; w < 8; w++) {
            unsigned m = s2w[cur][w];
            const float2* base = g_W2recT + (w * 32) * 128 + l;
            while (m) {
                int j = __ffs((int)m) - 1;
                m &= m - 1;
                float2 v = base[j * 128];
                i2a += v.x; i2b += v.y;
            }
        }

        // ALIF update (uses previous spike in both adaptation and reset)
        a2a = rh_a * a2a + (1.0f - rh_a) * s2a;
        a2b = rh_b * a2b + (1.0f - rh_b) * s2b;
        float Ba = B_J0 + BETA * a2a;
        float Bb = B_J0 + BETA * a2b;
        m2a = al_a * m2a + (1.0f - al_a) * i2a - Ba * s2a;
        m2b = al_b * m2b + (1.0f - al_b) * i2b - Bb * s2b;
        s2a = (m2a - Ba > 0.f) ? 1.f : 0.f;
        s2b = (m2b - Bb > 0.f) ? 1.f : 0.f;

        unsigned bala = __ballot_sync(0xffffffffu, s2a > 0.5f);
        unsigned balb = __ballot_sync(0xffffffffu, s2b > 0.5f);
        if ((l & 31) == 0) {
            s2w[nxt][wid]     = bala;
            s2w[nxt][wid + 4] = balb;
        }
        __syncthreads();

        // layer 3 (threads 0..11), uses the NEW s2
        if (l < OUTN) {
            float i3 = b3v;
            const float* wr = &W3s[l * 257];
            #pragma unroll
            for (int w = 0; w < 8; w++) {
                unsigned m = s2w[nxt][w];
                int base = w * 32;
                while (m) {
                    int j = __ffs((int)m) - 1;
                    m &= m - 1;
                    i3 += wr[base + j];
                }
            }
            m3 = al3 * m3 + (1.0f - al3) * i3;
            accr += m3;
        }
    }
    if (l < OUTN) g_acc[b * OUTN + l] = accr;
}

// ------------------------- K4: log-softmax ----------------------------------
__global__ void __launch_bounds__(256)
k4_softmax(float* __restrict__ out)
{
    int b = blockIdx.x * 256 + threadIdx.x;
    if (b >= BB) return;
    float v[OUTN];
    float mx = -1e30f;
    #pragma unroll
    for (int o = 0; o < OUTN; o++) {
        v[o] = g_acc[b * OUTN + o] * (1.0f / (float)TT);
        mx = fmaxf(mx, v[o]);
    }
    float sum = 0.f;
    #pragma unroll
    for (int o = 0; o < OUTN; o++) sum += __expf(v[o] - mx);
    float lse = mx + __logf(sum);
    #pragma unroll
    for (int o = 0; o < OUTN; o++) out[b * OUTN + o] = v[o] - lse;
}

// ------------------------- launch -------------------------------------------
extern "C" void kernel_launch(void* const* d_in, const int* in_sizes, int n_in,
                              void* d_out, int out_size)
{
    const float* x        = (const float*)d_in[0];
    const float* thr      = (const float*)d_in[1];
    const float* W1       = (const float*)d_in[2];
    const float* b1       = (const float*)d_in[3];
    const float* W2_in    = (const float*)d_in[4];
    const float* b2_in    = (const float*)d_in[5];
    const float* W2_rec   = (const float*)d_in[6];
    const float* b2_rec   = (const float*)d_in[7];
    const float* W3       = (const float*)d_in[8];
    const float* b3       = (const float*)d_in[9];
    const float* tau_adp1 = (const float*)d_in[10];
    const float* tau_m1   = (const float*)d_in[11];
    const float* tau_adp2 = (const float*)d_in[12];
    const float* tau_m2   = (const float*)d_in[13];
    const float* tau_m3   = (const float*)d_in[14];
    float* out = (float*)d_out;

    static_assert(sizeof(float2) == 8, "");

    cudaFuncSetAttribute(k1_gemm1, cudaFuncAttributeMaxDynamicSharedMemorySize, 153600);

    k0_transpose<<<NN, 128>>>(W2_in, W2_rec);
    k1_gemm1<<<(TT * BB) / 64, 256, 153600>>>(x, thr, W1, b1);
    k2_scan1<<<BB, 256>>>(tau_adp1, tau_m1);
    k3_recurrent<<<BB, 128>>>(b2_in, b2_rec, W3, b3, tau_adp2, tau_m2, tau_m3);
    k4_softmax<<<(BB + 255) / 256, 256>>>(out);
}

// round 3
// speedup vs baseline: 1.5646x; 1.5646x over previous
#include <cuda_runtime.h>
#include <cuda_bf16.h>
#include <cstdint>

#define BB   512
#define CC   3
#define TT   500
#define DD   40
#define CD   120
#define NN   256
#define OUTN 12
#define BN   (BB*NN)        // 131072
#define SW   (BN/32)        // 4096 bit-words per timestep
#define B_J0 0.01f
#define BETA 1.8f

// ------------------------- device scratch (allocation-guard-safe) -----------
__device__ float    g_i1[(size_t)TT * BB * NN];     // 262 MB
__device__ unsigned g_s1[(size_t)TT * SW];          // 8.2 MB
__device__ float2   g_W2inT[NN * 128];              // [j][pair(l, l+128)]
__device__ float2   g_W2recT[NN * 128];
__device__ float    g_acc[BB * OUTN];

// ------------------------- packed f32x2 helpers -----------------------------
__device__ __forceinline__ unsigned long long pack_dup(float a) {
    unsigned long long r;
    asm("mov.b64 %0, {%1,%1};" : "=l"(r) : "f"(a));
    return r;
}
__device__ __forceinline__ void unpack2(unsigned long long v, float& a, float& b) {
    asm("mov.b64 {%0,%1}, %2;" : "=f"(a), "=f"(b) : "l"(v));
}
__device__ __forceinline__ void fma2(unsigned long long& acc,
                                     unsigned long long a, unsigned long long b) {
    asm("fma.rn.f32x2 %0, %1, %2, %0;" : "+l"(acc) : "l"(a), "l"(b));
}

// ------------------------- K0: transpose W2 matrices ------------------------
__global__ void k0_transpose(const float* __restrict__ W2_in,
                             const float* __restrict__ W2_rec)
{
    int j = blockIdx.x;        // presyn neuron 0..255
    int l = threadIdx.x;       // 0..127
    g_W2inT [j * 128 + l] = make_float2(W2_in [l * NN + j], W2_in [(l + 128) * NN + j]);
    g_W2recT[j * 128 + l] = make_float2(W2_rec[l * NN + j], W2_rec[(l + 128) * NN + j]);
}

// ------------------------- K1: spikify + i1 GEMM ----------------------------
// grid 4000 blocks x 256 threads. Block: 64 rows (one t, b0..b0+63) x 256 n.
// Register tile: 8 rows x 8 n per thread (f32x2 packed).
// smem: w1t[120][256] f32 (122880) + xs2[120][64] ull-dup (61440)
//       + stage[64][121] f32 (30976) = 215296 B
#define K1_SMEM (CD*NN*4 + CD*64*8 + 64*121*4)
__global__ void __launch_bounds__(256, 1)
k1_gemm1(const float* __restrict__ x, const float* __restrict__ thrp,
         const float* __restrict__ W1, const float* __restrict__ b1)
{
    extern __shared__ float sm[];
    float*              w1t   = sm;                                  // [k][n]
    unsigned long long* xs2   = (unsigned long long*)(sm + CD * NN); // [k][r] dup
    float*              stage = (float*)(xs2 + CD * 64);             // [r][121]

    const int tid = threadIdx.x;
    const int p0  = blockIdx.x * 64;
    const int t   = p0 >> 9;
    const int b0  = p0 & 511;
    const float thr = *thrp;

    // ---- W1 -> transposed smem: each thread streams its own W1 row (n = tid)
    {
        const int n = tid;
        const float4* wr = (const float4*)(W1 + n * CD);
        #pragma unroll 5
        for (int q = 0; q < 30; q++) {
            float4 v = wr[q];
            int k = q * 4;
            w1t[(k + 0) * NN + n] = v.x;   // coalesced across lanes (n consecutive)
            w1t[(k + 1) * NN + n] = v.y;
            w1t[(k + 2) * NN + n] = v.z;
            w1t[(k + 3) * NN + n] = v.w;
        }
    }
    // ---- pass A: spikify into stage[r][cd] (coalesced LDG + coalesced STS)
    for (int i = tid; i < 64 * CD; i += 256) {
        int r  = i / CD;
        int cd = i % CD;
        int c  = cd / DD, d = cd % DD;
        int b  = b0 + r;
        float xv = x[(((size_t)b * CC + c) * TT + t) * DD + d];
        float s  = (xv > thr) ? 1.0f : ((xv < -thr) ? -1.0f : 0.0f);
        stage[r * 121 + cd] = s;
    }
    __syncthreads();
    // ---- pass B: transpose stage -> xs2[k][r] duplicated f32x2
    for (int i = tid; i < CD * 64; i += 256) {
        int cd = i >> 6;
        int r  = i & 63;
        xs2[cd * 64 + r] = pack_dup(stage[r * 121 + cd]);  // stride-121 LDS: conflict-free
    }
    __syncthreads();

    // ---- main: 8 rows x 8 n per thread
    const int ng = tid & 31;   // n-group: n = ng*8 .. ng*8+7
    const int rg = tid >> 5;   // row-group: rows rg*8 .. rg*8+7
    unsigned long long acc[32];
    #pragma unroll
    for (int i = 0; i < 32; i++) acc[i] = 0ull;

    #pragma unroll 2
    for (int k = 0; k < CD; k++) {
        const ulonglong2* wp = (const ulonglong2*)(w1t + k * NN + (ng << 3));
        ulonglong2 wA = wp[0];        // n pairs 0,1
        ulonglong2 wB = wp[1];        // n pairs 2,3
        const ulonglong2* xp = (const ulonglong2*)(xs2 + k * 64 + (rg << 3));
        ulonglong2 x01 = xp[0], x23 = xp[1], x45 = xp[2], x67 = xp[3];
        unsigned long long xd[8] = {x01.x, x01.y, x23.x, x23.y,
                                    x45.x, x45.y, x67.x, x67.y};
        #pragma unroll
        for (int rr = 0; rr < 8; rr++) {
            fma2(acc[rr * 4 + 0], xd[rr], wA.x);
            fma2(acc[rr * 4 + 1], xd[rr], wA.y);
            fma2(acc[rr * 4 + 2], xd[rr], wB.x);
            fma2(acc[rr * 4 + 3], xd[rr], wB.y);
        }
    }

    // ---- epilogue: add bias, store
    float4 bq0 = *(const float4*)(b1 + (ng << 3));
    float4 bq1 = *(const float4*)(b1 + (ng << 3) + 4);
    #pragma unroll
    for (int rr = 0; rr < 8; rr++) {
        float o[8];
        #pragma unroll
        for (int np = 0; np < 4; np++)
            unpack2(acc[rr * 4 + np], o[2 * np], o[2 * np + 1]);
        o[0] += bq0.x; o[1] += bq0.y; o[2] += bq0.z; o[3] += bq0.w;
        o[4] += bq1.x; o[5] += bq1.y; o[6] += bq1.z; o[7] += bq1.w;
        size_t base = (size_t)t * BN + (size_t)(b0 + rg * 8 + rr) * NN + (ng << 3);
        *(float4*)&g_i1[base]     = make_float4(o[0], o[1], o[2], o[3]);
        *(float4*)&g_i1[base + 4] = make_float4(o[4], o[5], o[6], o[7]);
    }
}

// ------------------------- K2: layer-1 ALIF scan -> s1 bits -----------------
__global__ void __launch_bounds__(256)
k2_scan1(const float* __restrict__ tau_adp1, const float* __restrict__ tau_m1)
{
    const int gid  = blockIdx.x * 256 + threadIdx.x;  // b*256 + n
    const int nidx = gid & 255;
    const int lane = threadIdx.x & 31;
    const unsigned wordIdx = gid >> 5;                // b*8 + n/32

    const float alpha = __expf(-1.0f / tau_m1[nidx]);
    const float rho   = __expf(-1.0f / tau_adp1[nidx]);
    const float ca = 1.0f - alpha, cr = 1.0f - rho;

    float m = 0.f, a = B_J0, s = 0.f;
    const float* ip = g_i1 + gid;

    for (int t = 0; t < TT; t += 4) {
        float iv[4];
        #pragma unroll
        for (int k = 0; k < 4; k++) iv[k] = ip[(size_t)(t + k) * BN];
        #pragma unroll
        for (int k = 0; k < 4; k++) {
            a = rho * a + cr * s;
            float Bth = B_J0 + BETA * a;
            m = alpha * m + ca * iv[k] - Bth * s;
            s = (m - Bth > 0.f) ? 1.f : 0.f;
            unsigned bal = __ballot_sync(0xffffffffu, s > 0.5f);
            if (lane == 0) g_s1[(size_t)(t + k) * SW + wordIdx] = bal;
        }
    }
}

// ------------------------- K3: sequential layer-2 + layer-3 -----------------
// grid 512 blocks (one per batch) x 128 threads (thread l owns neurons l, l+128).
// Per step: compact spike masks into index lists (no serial ffs chain in the
// hot gather), then counted unrolled gather loops with batched LDG.64.
__global__ void __launch_bounds__(128)
k3_recurrent(const float* __restrict__ b2_in,  const float* __restrict__ b2_rec,
             const float* __restrict__ W3,     const float* __restrict__ b3,
             const float* __restrict__ tau_adp2, const float* __restrict__ tau_m2,
             const float* __restrict__ tau_m3)
{
    __shared__ float    W3s[OUTN * 257];
    __shared__ unsigned words[16];        // [0..7]=s1, [8..15]=s2(prev)
    __shared__ int      lst1[256];
    __shared__ int      lst2[256];

    const int b   = blockIdx.x;
    const int l   = threadIdx.x;
    const int lane = l & 31;
    const int wid  = l >> 5;

    for (int i = l; i < OUTN * NN; i += 128)
        W3s[(i >> 8) * 257 + (i & 255)] = W3[i];
    if (l < 8) words[8 + l] = 0u;

    const int n0 = l, n1 = l + 128;
    const float al_a = __expf(-1.0f / tau_m2[n0]),   al_b = __expf(-1.0f / tau_m2[n1]);
    const float rh_a = __expf(-1.0f / tau_adp2[n0]), rh_b = __expf(-1.0f / tau_adp2[n1]);
    const float bia  = b2_in[n0] + b2_rec[n0];
    const float bib  = b2_in[n1] + b2_rec[n1];

    float m2a = 0.f, m2b = 0.f, a2a = B_J0, a2b = B_J0, s2a = 0.f, s2b = 0.f;

    float al3 = 1.f, m3 = 0.f, accr = 0.f, b3v = 0.f;
    if (l < OUTN) { al3 = __expf(-1.0f / tau_m3[l]); b3v = b3[l]; }

    const float2* __restrict__ w2i = g_W2inT;
    const float2* __restrict__ w2r = g_W2recT;
    const unsigned s1base = (unsigned)b * 8;
    __syncthreads();

    int cnt1 = 0, cnt2 = 0;

    for (int t = 0; t < TT; t++) {
        if (l < 8) words[l] = g_s1[(size_t)t * SW + s1base + l];
        __syncthreads();   // s1 words + prev-step s2 ballots visible

        // deferred layer-3 for step t-1 (only warp 0 lanes 0..11; overlaps compaction)
        if (l < OUTN && t > 0) {
            float i3 = b3v;
            const float* wr = &W3s[l * 257];
            #pragma unroll
            for (int w = 0; w < 8; w++) {
                unsigned m = words[8 + w];
                int base = w * 32;
                while (m) {
                    int j = __ffs((int)m) - 1;
                    m &= m - 1;
                    i3 += wr[base + j];
                }
            }
            m3 = al3 * m3 + (1.0f - al3) * i3;
            accr += m3;
        }

        // compaction: every thread popcounts all 16 broadcast words
        unsigned wv[16];
        #pragma unroll
        for (int w = 0; w < 16; w++) wv[w] = words[w];
        int offA[8], offB[8];
        {
            int o = 0;
            #pragma unroll
            for (int w = 0; w < 8; w++) { offA[w] = o; o += __popc(wv[w]); }
            cnt1 = o;
            o = 0;
            #pragma unroll
            for (int w = 0; w < 8; w++) { offB[w] = o; o += __popc(wv[8 + w]); }
            cnt2 = o;
        }
        {
            const unsigned ltm = (1u << lane) - 1u;
            #pragma unroll
            for (int g = 0; g < 4; g++) {
                int w = wid + g * 4;                 // covers 0..15
                unsigned wd = wv[w];
                if ((wd >> lane) & 1u) {
                    int pos = __popc(wd & ltm);
                    if (w < 8) lst1[offA[w] + pos]     = w * 32 + lane;
                    else       lst2[offB[w - 8] + pos] = (w - 8) * 32 + lane;
                }
            }
        }
        __syncthreads();   // lists ready

        // gather (counted, unrolled-by-4, independent LDG.64s)
        float i2a = bia, i2b = bib;
        {
            int k = 0;
            for (; k + 4 <= cnt1; k += 4) {
                int j0 = lst1[k], j1 = lst1[k+1], j2 = lst1[k+2], j3 = lst1[k+3];
                float2 v0 = w2i[j0 * 128 + l];
                float2 v1 = w2i[j1 * 128 + l];
                float2 v2 = w2i[j2 * 128 + l];
                float2 v3 = w2i[j3 * 128 + l];
                i2a += v0.x; i2b += v0.y;
                i2a += v1.x; i2b += v1.y;
                i2a += v2.x; i2b += v2.y;
                i2a += v3.x; i2b += v3.y;
            }
            for (; k < cnt1; k++) {
                int j = lst1[k];
                float2 v = w2i[j * 128 + l];
                i2a += v.x; i2b += v.y;
            }
            k = 0;
            for (; k + 4 <= cnt2; k += 4) {
                int j0 = lst2[k], j1 = lst2[k+1], j2 = lst2[k+2], j3 = lst2[k+3];
                float2 v0 = w2r[j0 * 128 + l];
                float2 v1 = w2r[j1 * 128 + l];
                float2 v2 = w2r[j2 * 128 + l];
                float2 v3 = w2r[j3 * 128 + l];
                i2a += v0.x; i2b += v0.y;
                i2a += v1.x; i2b += v1.y;
                i2a += v2.x; i2b += v2.y;
                i2a += v3.x; i2b += v3.y;
            }
            for (; k < cnt2; k++) {
                int j = lst2[k];
                float2 v = w2r[j * 128 + l];
                i2a += v.x; i2b += v.y;
            }
        }

        // ALIF update (previous spike enters adaptation and reset)
        a2a = rh_a * a2a + (1.0f - rh_a) * s2a;
        a2b = rh_b * a2b + (1.0f - rh_b) * s2b;
        float Ba = B_J0 + BETA * a2a;
        float Bb = B_J0 + BETA * a2b;
        m2a = al_a * m2a + (1.0f - al_a) * i2a - Ba * s2a;
        m2b = al_b * m2b + (1.0f - al_b) * i2b - Bb * s2b;
        s2a = (m2a - Ba > 0.f) ? 1.f : 0.f;
        s2b = (m2b - Bb > 0.f) ? 1.f : 0.f;

        unsigned bala = __ballot_sync(0xffffffffu, s2a > 0.5f);
        unsigned balb = __ballot_sync(0xffffffffu, s2b > 0.5f);
        if (lane == 0) {
            words[8 + wid]  = bala;   // neurons wid*32..+31
            words[12 + wid] = balb;   // neurons 128+wid*32..+31
        }
        // next iteration's first __syncthreads makes these visible
    }

    // final deferred layer-3 for step TT-1
    __syncthreads();
    if (l < OUTN) {
        float i3 = b3v;
        const float* wr = &W3s[l * 257];
        #pragma unroll
        for (int w = 0; w < 8; w++) {
            unsigned m = words[8 + w];
            int base = w * 32;
            while (m) {
                int j = __ffs((int)m) - 1;
                m &= m - 1;
                i3 += wr[base + j];
            }
        }
        m3 = al3 * m3 + (1.0f - al3) * i3;
        accr += m3;
        g_acc[b * OUTN + l] = accr;
    }
}

// ------------------------- K4: log-softmax ----------------------------------
__global__ void __launch_bounds__(256)
k4_softmax(float* __restrict__ out)
{
    int b = blockIdx.x * 256 + threadIdx.x;
    if (b >= BB) return;
    float v[OUTN];
    float mx = -1e30f;
    #pragma unroll
    for (int o = 0; o < OUTN; o++) {
        v[o] = g_acc[b * OUTN + o] * (1.0f / (float)TT);
        mx = fmaxf(mx, v[o]);
    }
    float sum = 0.f;
    #pragma unroll
    for (int o = 0; o < OUTN; o++) sum += __expf(v[o] - mx);
    float lse = mx + __logf(sum);
    #pragma unroll
    for (int o = 0; o < OUTN; o++) out[b * OUTN + o] = v[o] - lse;
}

// ------------------------- launch -------------------------------------------
extern "C" void kernel_launch(void* const* d_in, const int* in_sizes, int n_in,
                              void* d_out, int out_size)
{
    const float* x        = (const float*)d_in[0];
    const float* thr      = (const float*)d_in[1];
    const float* W1       = (const float*)d_in[2];
    const float* b1       = (const float*)d_in[3];
    const float* W2_in    = (const float*)d_in[4];
    const float* b2_in    = (const float*)d_in[5];
    const float* W2_rec   = (const float*)d_in[6];
    const float* b2_rec   = (const float*)d_in[7];
    const float* W3       = (const float*)d_in[8];
    const float* b3       = (const float*)d_in[9];
    const float* tau_adp1 = (const float*)d_in[10];
    const float* tau_m1   = (const float*)d_in[11];
    const float* tau_adp2 = (const float*)d_in[12];
    const float* tau_m2   = (const float*)d_in[13];
    const float* tau_m3   = (const float*)d_in[14];
    float* out = (float*)d_out;

    cudaFuncSetAttribute(k1_gemm1, cudaFuncAttributeMaxDynamicSharedMemorySize, K1_SMEM);

    k0_transpose<<<NN, 128>>>(W2_in, W2_rec);
    k1_gemm1<<<(TT * BB) / 64, 256, K1_SMEM>>>(x, thr, W1, b1);
    k2_scan1<<<BB, 256>>>(tau_adp1, tau_m1);
    k3_recurrent<<<BB, 128>>>(b2_in, b2_rec, W3, b3, tau_adp2, tau_m2, tau_m3);
    k4_softmax<<<(BB + 255) / 256, 256>>>(out);
}